// round 16
// baseline (speedup 1.0000x reference)
#include <cuda_runtime.h>
#include <cuda_fp16.h>
#include <cstdint>

// ---------------------------------------------------------------------------
// Problem constants
// ---------------------------------------------------------------------------
namespace {
constexpr int kB   = 8;
constexpr int kN   = 4096;
constexpr int kE   = 128;   // Din  (GEMM K)
constexpr int kF   = 256;   // Dout (GEMM M)
constexpr int kPTS = 32;    // points per block
constexpr int kM   = 3 * kPTS;  // 96 = GEMM N
constexpr int kT   = 256;   // 8 warps

// smem layout (bytes). fp16 everywhere. Row stride 272 B (136 fp16: 128 data
// + 8 pad) -> word stride 68, 68%32=4: all fragment loads conflict-free.
constexpr int ROW_B   = 272;
constexpr int OFF_A   = 0;
constexpr int A_BYTES = kM * ROW_B;            // 26112
constexpr int W_BYTES = kF * ROW_B;            // 69632 (one full weight [256][128] fp16)
constexpr int OFF_WX  = A_BYTES;               // Mc   26112
constexpr int OFF_WD  = OFF_WX + W_BYTES;      // W2   95744
constexpr int SMEM_BYTES = OFF_WD + W_BYTES;   // 165376 B
}

// ---------------------------------------------------------------------------
// Per-launch folded weights (device globals — no allocation allowed)
// ---------------------------------------------------------------------------
__device__ __align__(16) __half g_McH[kF * kE];   // fp16 Mc = A+B+C
__device__ __align__(16) __half g_W2H[kF * kE];   // fp16 W2 = W @ Mc

// ---------------------------------------------------------------------------
// Small helpers
// ---------------------------------------------------------------------------
__device__ __forceinline__ uint32_t smem_u32(const void* p) {
    uint32_t a;
    asm("{ .reg .u64 t; cvta.to.shared.u64 t, %1; cvt.u32.u64 %0, t; }" : "=r"(a) : "l"(p));
    return a;
}
__device__ __forceinline__ void cp16(uint32_t dst, const void* src) {
    asm volatile("cp.async.cg.shared.global [%0], [%1], 16;"
                 :: "r"(dst), "l"(__cvta_generic_to_global(src)) : "memory");
}
__device__ __forceinline__ void cp_commit() {
    asm volatile("cp.async.commit_group;" ::: "memory");
}
template <int N>
__device__ __forceinline__ void cp_wait() {
    asm volatile("cp.async.wait_group %0;" :: "n"(N) : "memory");
}

// mma.sync m16n8k16 fp16->f32 (sm_80 baseline — compiles under compute_103)
__device__ __forceinline__ void mma_f16(float (&c)[4], const uint32_t (&a)[4],
                                        const uint32_t (&b)[2]) {
    asm volatile(
        "mma.sync.aligned.m16n8k16.row.col.f32.f16.f16.f32 "
        "{%0,%1,%2,%3}, {%4,%5,%6,%7}, {%8,%9}, {%0,%1,%2,%3};"
        : "+f"(c[0]), "+f"(c[1]), "+f"(c[2]), "+f"(c[3])
        : "r"(a[0]), "r"(a[1]), "r"(a[2]), "r"(a[3]), "r"(b[0]), "r"(b[1]));
}

// ---------------------------------------------------------------------------
// Fused prep: one kernel, 256 blocks x 128 threads.
// Block o: McH row o, and W2H row o = (W row o) . Mc  (Mc recomputed from
// A+B+C — inputs are 128 KB each, fully L2-resident across blocks).
// ---------------------------------------------------------------------------
__global__ __launch_bounds__(128)
void prep_all(const float* __restrict__ Am, const float* __restrict__ Bm,
              const float* __restrict__ Cm, const float* __restrict__ Wd) {
    __shared__ float wrow[kF];
    const int o = blockIdx.x;
    const int e = threadIdx.x;
    for (int c = threadIdx.x; c < kF; c += 128) wrow[c] = Wd[o * kF + c];

    // Mc row o (this block's own row)
    {
        const int i = o * kE + e;
        g_McH[i] = __float2half_rn(Am[i] + Bm[i] + Cm[i]);
    }
    __syncthreads();

    float acc = 0.0f;
    #pragma unroll 8
    for (int c = 0; c < kF; ++c) {
        const int i = c * kE + e;
        acc = fmaf(wrow[c], Am[i] + Bm[i] + Cm[i], acc);
    }
    g_W2H[o * kE + e] = __float2half_rn(acc);
}

// ---------------------------------------------------------------------------
// Main fused kernel
// ---------------------------------------------------------------------------
__global__ __launch_bounds__(kT, 1)
void affine_vn_f16(const float* __restrict__ X, const float* __restrict__ J,
                   float* __restrict__ out)
{
    extern __shared__ char smem[];
    const uint32_t sb = smem_u32(smem);
    const int t    = threadIdx.x;
    const int wid  = t >> 5;
    const int lane = t & 31;
    const int b    = blockIdx.y;
    const int n0   = blockIdx.x * kPTS;

    // ---- Issue the ENTIRE weight set (Mc + W2, 128 KB fp16) as cp.async ----
    // 512 rows x 16 cp16/row = 8192; 32 per thread. Streams during phase 1.
    #pragma unroll
    for (int it = 0; it < 16; ++it) {
        const int q = it * kT + t;             // 0..4095
        const int f = q >> 4, j = q & 15;
        const size_t gi = (size_t)f * kE + j * 8;
        const uint32_t so = (uint32_t)(f * ROW_B + j * 16);
        cp16(sb + OFF_WX + so, g_McH + gi);
        cp16(sb + OFF_WD + so, g_W2H + gi);
    }
    cp_commit();

    // ---- Phase 1: rotations + projections -> a-tile fp16 [slot][e] ----
    // point->m permutation so each lane owns complete (i=0,1,2) triples:
    //   p = 16h + 4tt + j ; slot(p,i) = 48h + 8*((3j+i)>>1) + 2tt + ((3j+i)&1)
    __half* a_h = reinterpret_cast<__half*>(smem + OFF_A);
    #pragma unroll 4
    for (int it = 0; it < 16; ++it) {
        const int q  = it * kT + t;
        const int e  = q & (kE - 1);
        const int p  = q >> 7;          // point 0..31
        const size_t base = (size_t)(b * kN + n0 + p) * kE + e;
        const float* xp = X + base * 3;
        const float* jp = J + base * 6;
        const float x0 = xp[0], x1 = xp[1], x2 = xp[2];
        const float u0 = jp[0], u1 = jp[2], u2 = jp[4];
        const float v0 = jp[1], v1 = jp[3], v2 = jp[5];

        const float nn  = u0*u0 + u1*u1 + u2*u2;
        const float iv1 = rsqrtf(fmaxf(nn, 1e-24f));
        const float b10 = u0*iv1, b11 = u1*iv1, b12 = u2*iv1;
        const float dp  = b10*v0 + b11*v1 + b12*v2;
        const float w0 = v0 - dp*b10, w1 = v1 - dp*b11, w2 = v2 - dp*b12;
        const float wn  = w0*w0 + w1*w1 + w2*w2;
        const float iv2 = rsqrtf(fmaxf(wn, 1e-24f));
        const float b20 = w0*iv2, b21 = w1*iv2, b22 = w2*iv2;
        const float b30 = b11*b22 - b12*b21;
        const float b31 = b12*b20 - b10*b22;
        const float b32 = b10*b21 - b11*b20;

        float av[3];
        av[0] = x0*b10 + x1*b11 + x2*b12;
        av[1] = x0*b20 + x1*b21 + x2*b22;
        av[2] = x0*b30 + x1*b31 + x2*b32;

        const int h  = p >> 4;
        const int qq = p & 15;
        const int tt = qq >> 2;
        const int jj = qq & 3;
        #pragma unroll
        for (int i = 0; i < 3; ++i) {
            const int idx  = 3 * jj + i;
            const int slot = 48 * h + 8 * (idx >> 1) + 2 * tt + (idx & 1);
            a_h[slot * (ROW_B / 2) + e] = __float2half_rn(av[i]);
        }
    }

    // ---- single rendezvous: weights landed + a-tile published ----
    cp_wait<0>();
    __syncthreads();

    // ---- Fused GEMMs, barrier-free mainloop: 8 k-steps of 16 ----
    float accx[4][6][4], accd[4][6][4];
    #pragma unroll
    for (int i = 0; i < 4; ++i)
        #pragma unroll
        for (int j = 0; j < 6; ++j)
            #pragma unroll
            for (int q = 0; q < 4; ++q) { accx[i][j][q] = 0.0f; accd[i][j][q] = 0.0f; }

    {
        const int f0w = (wid & 3) * 64;     // f-quarter
        const int mh  = (wid >> 2) * 48;    // m-half
        const int g   = lane >> 2;          // 0..7
        const int k   = lane & 3;           // 0..3
        const uint32_t* as = reinterpret_cast<const uint32_t*>(smem + OFF_A);
        const uint32_t* wx = reinterpret_cast<const uint32_t*>(smem + OFF_WX);
        const uint32_t* wd = reinterpret_cast<const uint32_t*>(smem + OFF_WD);
        constexpr int RW = ROW_B / 4;       // row stride in words (68)

        #pragma unroll
        for (int kc = 0; kc < 8; ++kc) {
            const int c0 = kc * 8 + k;      // word column

            uint32_t bfr[6][2];
            #pragma unroll
            for (int n = 0; n < 6; ++n) {
                const int row = (mh + n * 8 + g) * RW;
                bfr[n][0] = as[row + c0];
                bfr[n][1] = as[row + c0 + 4];
            }

            #pragma unroll
            for (int tf = 0; tf < 4; ++tf) {
                const int r0 = (f0w + tf * 16 + g) * RW;
                uint32_t a[4];
                a[0] = wx[r0 + c0];
                a[1] = wx[r0 + 8 * RW + c0];
                a[2] = wx[r0 + c0 + 4];
                a[3] = wx[r0 + 8 * RW + c0 + 4];
                #pragma unroll
                for (int n = 0; n < 6; ++n) mma_f16(accx[tf][n], a, bfr[n]);

                a[0] = wd[r0 + c0];
                a[1] = wd[r0 + 8 * RW + c0];
                a[2] = wd[r0 + c0 + 4];
                a[3] = wd[r0 + 8 * RW + c0 + 4];
                #pragma unroll
                for (int n = 0; n < 6; ++n) mma_f16(accd[tf][n], a, bfr[n]);
            }
        }
    }

    // ---- Epilogue: VN-LeakyReLU fully in registers + float4 stores ----
    {
        const int f0w = (wid & 3) * 64;
        const int h   = wid >> 2;
        const int g   = lane >> 2;
        const int tt  = lane & 3;
        #pragma unroll
        for (int tf = 0; tf < 4; ++tf) {
            #pragma unroll
            for (int ch = 0; ch < 2; ++ch) {
                const int f = f0w + tf * 16 + ch * 8 + g;
                float res[3][4];
                #pragma unroll
                for (int j = 0; j < 4; ++j) {
                    float xv[3], dv[3];
                    #pragma unroll
                    for (int i = 0; i < 3; ++i) {
                        const int idx = 3 * j + i;
                        xv[i] = accx[tf][idx >> 1][(idx & 1) + 2 * ch];
                        dv[i] = accd[tf][idx >> 1][(idx & 1) + 2 * ch];
                    }
                    const float dot = xv[0]*dv[0] + xv[1]*dv[1] + xv[2]*dv[2];
                    const float dsq = dv[0]*dv[0] + dv[1]*dv[1] + dv[2]*dv[2];
                    const float s = (dot >= 0.0f) ? 0.0f
                                  : 0.8f * dot * __fdividef(1.0f, dsq + 1e-6f);
                    res[0][j] = xv[0] - s * dv[0];
                    res[1][j] = xv[1] - s * dv[1];
                    res[2][j] = xv[2] - s * dv[2];
                }
                const size_t ob = ((size_t)(b * kF + f) * 3) * kN + n0 + 16 * h + 4 * tt;
                #pragma unroll
                for (int i = 0; i < 3; ++i) {
                    *reinterpret_cast<float4*>(out + ob + (size_t)i * kN) =
                        make_float4(res[i][0], res[i][1], res[i][2], res[i][3]);
                }
            }
        }
    }
}

// ---------------------------------------------------------------------------
// Launcher
// ---------------------------------------------------------------------------
extern "C" void kernel_launch(void* const* d_in, const int* in_sizes, int n_in,
                              void* d_out, int out_size) {
    (void)in_sizes; (void)n_in; (void)out_size;
    const float* X  = (const float*)d_in[0];
    const float* J  = (const float*)d_in[1];
    const float* Am = (const float*)d_in[2];
    const float* Bm = (const float*)d_in[3];
    const float* Cm = (const float*)d_in[4];
    const float* Wd = (const float*)d_in[5];
    float* out = (float*)d_out;

    prep_all<<<kF, 128>>>(Am, Bm, Cm, Wd);

    cudaFuncSetAttribute(affine_vn_f16,
                         cudaFuncAttributeMaxDynamicSharedMemorySize, SMEM_BYTES);
    dim3 grid(kN / kPTS, kB);
    affine_vn_f16<<<grid, kT, SMEM_BYTES>>>(X, J, out);
}